// round 11
// baseline (speedup 1.0000x reference)
#include <cuda_runtime.h>
#include <cuda_pipeline.h>
#include <math.h>

#define B 16384
#define TDEC 12
#define CHUNK_ELEMS 4096
#define NCHUNK 4
#define PB_PER_CHUNK 768      // 48 e * 4096 b / 256 rows
#define DB_PER_CHUNK 64       // 4096 / 64
#define CB (PB_PER_CHUNK + DB_PER_CHUNK)

typedef unsigned long long ull;

__device__ __align__(16) float g_P[48 * B * 4];
__device__ int g_cnt[NCHUNK];   // zero-init; self-resetting per launch
__device__ int g_done[NCHUNK];

// ---- f32x2 packed math (sm_103a) ----
__device__ __forceinline__ ull fma2(ull a, ull b, ull c) {
    ull d;
    asm("fma.rn.f32x2 %0, %1, %2, %3;" : "=l"(d) : "l"(a), "l"(b), "l"(c));
    return d;
}
__device__ __forceinline__ ull add2(ull a, ull b) {
    ull d;
    asm("add.rn.f32x2 %0, %1, %2;" : "=l"(d) : "l"(a), "l"(b));
    return d;
}
__device__ __forceinline__ ull pk2(float lo, float hi) {
    ull r;
    asm("mov.b64 %0, {%1, %2};" : "=l"(r) : "f"(lo), "f"(hi));
    return r;
}
__device__ __forceinline__ float2 upk2(ull v) {
    float2 f;
    asm("mov.b64 {%0, %1}, %2;" : "=f"(f.x), "=f"(f.y) : "l"(v));
    return f;
}

__device__ __forceinline__ float nfix(float v) {
    if (isnan(v)) return 0.f;
    return fminf(fmaxf(v, -3.4028234663852886e38f), 3.4028234663852886e38f);
}
__device__ __forceinline__ float fsigmoid(float s) {
    s = fminf(fmaxf(s, -30.f), 30.f);
    return __fdividef(1.f, 1.f + __expf(-s));
}
__device__ __forceinline__ float ftanh(float a) {
    a = fminf(fmaxf(a, -15.f), 15.f);
    float t = __expf(2.f * a);
    return 1.f - __fdividef(2.f, t + 1.f);
}

// ---- P-role smem layout (floats) ----
#define PT_TILE0 0
#define PT_TILE1 8448         // 64*132
#define PT_WT    16896        // 33*20 = 660 floats -> total 17556 floats (70.2KB)

// ---- D-role smem layout (floats), from R7 (measured 108us) ----
#define AW_OFF   0
#define AB_OFF   1728
#define WHH_OFF  1776
#define WIH_OFF  4848
#define BRZ_OFF  5232
#define BIN_OFF  5296
#define BHN_OFF  5328
#define CWX_OFF  5360
#define CB_OFF   5376
#define FCW_OFF  5380
#define FCB_OFF  5412
#define P_OFF    5424
#define RB_OFF   18480
#define SMEM_FLOATS (18480 + 8 * 288)   // 20784 floats = 83136 B

__device__ void precompute_role(int chunk, int r, const float* __restrict__ enc,
                                const float* __restrict__ comb_W, float* dsm)
{
    float* tile0 = &dsm[PT_TILE0];
    float* tile1 = &dsm[PT_TILE1];
    float* wT = &dsm[PT_WT];

    const int tid = threadIdx.x;
    const int w = tid >> 5;
    const int lane = tid & 31;

    for (int idx = tid; idx < 512; idx += 256) {
        int q = idx >> 4, i = (idx >> 2) & 3, j = idx & 3;
        wT[q * 20 + i * 4 + j] = comb_W[i * 132 + q * 4 + j];
    }

    const int e = r >> 4;
    const int seg = r & 15;
    const size_t base = (size_t)e * B + (size_t)chunk * CHUNK_ELEMS + seg * 256;
    const float4* ebase = (const float4*)enc;

#pragma unroll
    for (int rr = 0; rr < 8; rr++) {
        size_t row = base + w * 8 + rr;
        __pipeline_memcpy_async(&tile0[(w * 8 + rr) * 132 + lane * 4],
                                &ebase[row * 32 + lane], 16);
    }
    __pipeline_commit();

    for (int ti = 0; ti < 4; ti++) {
        float* cur = (ti & 1) ? tile1 : tile0;
        float* nxt = (ti & 1) ? tile0 : tile1;
        __pipeline_wait_prior(0);
        __syncthreads();
        if (ti < 3) {
#pragma unroll
            for (int rr = 0; rr < 8; rr++) {
                size_t row = base + (size_t)(ti + 1) * 64 + w * 8 + rr;
                __pipeline_memcpy_async(&nxt[(w * 8 + rr) * 132 + lane * 4],
                                        &ebase[row * 32 + lane], 16);
            }
            __pipeline_commit();
        }

        const int rl = w * 8 + (lane >> 2);
        const int c = lane & 3;
        float s0 = 0.f, s1 = 0.f, s2 = 0.f, s3 = 0.f;
#pragma unroll
        for (int k = 0; k < 8; k++) {
            int kp = (k + 2 * c) & 7;
            int q = 8 * c + kp;
            float4 v  = *(const float4*)&cur[rl * 132 + q * 4];
            float4 w0 = *(const float4*)&wT[q * 20 + 0];
            float4 w1 = *(const float4*)&wT[q * 20 + 4];
            float4 w2 = *(const float4*)&wT[q * 20 + 8];
            float4 w3 = *(const float4*)&wT[q * 20 + 12];
            s0 = fmaf(v.x, w0.x, s0); s0 = fmaf(v.y, w0.y, s0); s0 = fmaf(v.z, w0.z, s0); s0 = fmaf(v.w, w0.w, s0);
            s1 = fmaf(v.x, w1.x, s1); s1 = fmaf(v.y, w1.y, s1); s1 = fmaf(v.z, w1.z, s1); s1 = fmaf(v.w, w1.w, s1);
            s2 = fmaf(v.x, w2.x, s2); s2 = fmaf(v.y, w2.y, s2); s2 = fmaf(v.z, w2.z, s2); s2 = fmaf(v.w, w2.w, s2);
            s3 = fmaf(v.x, w3.x, s3); s3 = fmaf(v.y, w3.y, s3); s3 = fmaf(v.z, w3.z, s3); s3 = fmaf(v.w, w3.w, s3);
        }
        s0 += __shfl_xor_sync(0xffffffffu, s0, 1); s0 += __shfl_xor_sync(0xffffffffu, s0, 2);
        s1 += __shfl_xor_sync(0xffffffffu, s1, 1); s1 += __shfl_xor_sync(0xffffffffu, s1, 2);
        s2 += __shfl_xor_sync(0xffffffffu, s2, 1); s2 += __shfl_xor_sync(0xffffffffu, s2, 2);
        s3 += __shfl_xor_sync(0xffffffffu, s3, 1); s3 += __shfl_xor_sync(0xffffffffu, s3, 2);

        float v = s0;
        if (c == 1) v = s1; else if (c == 2) v = s2; else if (c == 3) v = s3;
        g_P[(base + (size_t)ti * 64) * 4 + w * 32 + lane] = v;
        __syncthreads();
    }

    // release: all stores visible, then signal
    __threadfence();
    __syncthreads();
    if (tid == 0) atomicAdd(&g_cnt[chunk], 1);
}

__device__ void decoder_role(int chunk, int d,
                             const float* __restrict__ y,
                             const float* __restrict__ hidden,
                             const float* __restrict__ attn_W, const float* __restrict__ attn_b,
                             const float* __restrict__ comb_W, const float* __restrict__ comb_b,
                             const float* __restrict__ w_ih, const float* __restrict__ w_hh,
                             const float* __restrict__ b_ih, const float* __restrict__ b_hh,
                             const float* __restrict__ fc_W, const float* __restrict__ fc_b,
                             float* __restrict__ out, float* dsm)
{
    const int tid = threadIdx.x;
    const int w = tid >> 5;
    const int lane = tid & 31;
    const int s = lane >> 3;
    const int el = lane & 7;
    const int b0blk = chunk * CHUNK_ELEMS + d * 64;
    const int b = b0blk + w * 8 + el;

    // weights staging (independent of P)
    for (int i = tid; i < 1728; i += 256) dsm[AW_OFF + i] = attn_W[i];
    if (tid < 48) dsm[AB_OFF + tid] = attn_b[tid];
    for (int i = tid; i < 3072; i += 256) {
        int g = i >> 5, j = i & 31, q = j >> 2, rr = j & 3;
        dsm[WHH_OFF + g * 32 + (((q + g) & 7) << 2) + rr] = w_hh[i];
    }
    for (int i = tid; i < 384; i += 256) dsm[WIH_OFF + i] = w_ih[i];
    if (tid < 64) dsm[BRZ_OFF + tid] = b_ih[tid] + b_hh[tid];
    else if (tid < 96) {
        dsm[BIN_OFF + tid - 64] = b_ih[tid];
        dsm[BHN_OFF + tid - 64] = b_hh[tid];
    }
    if (tid < 16) dsm[CWX_OFF + tid] = comb_W[(tid >> 2) * 132 + 128 + (tid & 3)];
    if (tid < 4) dsm[CB_OFF + tid] = comb_b[tid];
    if (tid < 32) dsm[FCW_OFF + tid] = fc_W[tid];
    if (tid == 0) dsm[FCB_OFF] = fc_b[0];

    // gate: wait for this chunk's P producers
    if (tid == 0) {
        while (atomicAdd(&g_cnt[chunk], 0) < PB_PER_CHUNK) __nanosleep(200);
        __threadfence();
    }
    __syncthreads();

    // stage P slice
    {
        float4* Pd = (float4*)&dsm[P_OFF];
        const float4* gP4 = (const float4*)g_P;
        for (int i = tid; i < 48 * 64; i += 256) {
            int e = i >> 6, pc = i & 63;
            Pd[pc * 51 + e] = __ldg(&gP4[(size_t)e * B + b0blk + pc]);
        }
    }
    __syncthreads();

    ull hp[16];
#pragma unroll
    for (int q = 0; q < 8; q++) {
        float4 hv = *(const float4*)(hidden + (size_t)b * 32 + 4 * q);
        hp[2 * q + 0] = pk2(hv.x, hv.y);
        hp[2 * q + 1] = pk2(hv.z, hv.w);
    }

    float4 yv = *(const float4*)(y + (size_t)b * 52);
    float xA = nfix(yv.x), xB = nfix(yv.y), xC = nfix(yv.z), xD = nfix(yv.w);

    const ulonglong2* Pw2 = (const ulonglong2*)&dsm[P_OFF];
    const int prow = (w * 8 + el) * 51;
    float* rbuf = &dsm[RB_OFF + w * 288 + el * 36];
    const ulonglong2* rb2 = (const ulonglong2*)rbuf;

    for (int t = 0; t < TDEC; t++) {
        ull xab = pk2(xA, xB), xcd = pk2(xC, xD);

        float ss = 0.f;
        ull c01 = 0, c23 = 0;
#pragma unroll
        for (int j = 0; j < 12; j++) {
            const int e = 4 * j + s;
            const ulonglong2* awr2 = (const ulonglong2*)&dsm[AW_OFF + e * 36];
            ull acc2 = pk2(dsm[AB_OFF + e], 0.f);
            ulonglong2 w0 = awr2[0];
            acc2 = fma2(xab, w0.x, acc2);
            acc2 = fma2(xcd, w0.y, acc2);
#pragma unroll
            for (int q = 0; q < 8; q++) {
                ulonglong2 wv = awr2[1 + q];
                acc2 = fma2(hp[2 * q + 0], wv.x, acc2);
                acc2 = fma2(hp[2 * q + 1], wv.y, acc2);
            }
            float2 ac = upk2(acc2);
            float ev = __expf(ac.x + ac.y);
            ss += ev;
            ull evv = pk2(ev, ev);
            ulonglong2 pv = Pw2[prow + e];
            c01 = fma2(evv, pv.x, c01);
            c23 = fma2(evv, pv.y, c23);
        }
#pragma unroll
        for (int o = 8; o <= 16; o <<= 1) {
            ss += __shfl_xor_sync(0xffffffffu, ss, o);
            c01 = add2(c01, __shfl_xor_sync(0xffffffffu, c01, o));
            c23 = add2(c23, __shfl_xor_sync(0xffffffffu, c23, o));
        }

        float inv = __fdividef(1.f, ss);
        float2 cA = upk2(c01), cB = upk2(c23);
        float4 cw0 = *(const float4*)&dsm[CWX_OFF + 0];
        float4 cw1 = *(const float4*)&dsm[CWX_OFF + 4];
        float4 cw2 = *(const float4*)&dsm[CWX_OFF + 8];
        float4 cw3 = *(const float4*)&dsm[CWX_OFF + 12];
        float X0 = fmaf(cA.x, inv, dsm[CB_OFF + 0]);
        X0 = fmaf(xA, cw0.x, X0); X0 = fmaf(xB, cw0.y, X0); X0 = fmaf(xC, cw0.z, X0); X0 = fmaf(xD, cw0.w, X0);
        float X1 = fmaf(cA.y, inv, dsm[CB_OFF + 1]);
        X1 = fmaf(xA, cw1.x, X1); X1 = fmaf(xB, cw1.y, X1); X1 = fmaf(xC, cw1.z, X1); X1 = fmaf(xD, cw1.w, X1);
        float X2 = fmaf(cB.x, inv, dsm[CB_OFF + 2]);
        X2 = fmaf(xA, cw2.x, X2); X2 = fmaf(xB, cw2.y, X2); X2 = fmaf(xC, cw2.z, X2); X2 = fmaf(xD, cw2.w, X2);
        float X3 = fmaf(cB.y, inv, dsm[CB_OFF + 3]);
        X3 = fmaf(xA, cw3.x, X3); X3 = fmaf(xB, cw3.y, X3); X3 = fmaf(xC, cw3.z, X3); X3 = fmaf(xD, cw3.w, X3);
        ull X01 = pk2(X0, X1), X23 = pk2(X2, X3);

        float po = 0.f;
        const ulonglong2* wi2 = (const ulonglong2*)&dsm[WIH_OFF];
#pragma unroll
        for (int k = 0; k < 8; k++) {
            const int g = 4 * k + s;
            const int gz = 32 + g, gn = 64 + g;

            ulonglong2 wiv = wi2[g];
            ull a2 = fma2(X01, wiv.x, pk2(dsm[BRZ_OFF + g], 0.f));
            a2 = fma2(X23, wiv.y, a2);
            const ulonglong2* wp = (const ulonglong2*)&dsm[WHH_OFF + g * 32];
#pragma unroll
            for (int q = 0; q < 8; q++) {
                ulonglong2 wv = wp[(q + g) & 7];
                a2 = fma2(hp[2 * q + 0], wv.x, a2);
                a2 = fma2(hp[2 * q + 1], wv.y, a2);
            }
            float2 au = upk2(a2);
            float sr = au.x + au.y;

            ulonglong2 wzv = wi2[gz];
            ull z2 = fma2(X01, wzv.x, pk2(dsm[BRZ_OFF + gz], 0.f));
            z2 = fma2(X23, wzv.y, z2);
            const ulonglong2* wzp = (const ulonglong2*)&dsm[WHH_OFF + gz * 32];
#pragma unroll
            for (int q = 0; q < 8; q++) {
                ulonglong2 wv = wzp[(q + gz) & 7];
                z2 = fma2(hp[2 * q + 0], wv.x, z2);
                z2 = fma2(hp[2 * q + 1], wv.y, z2);
            }
            float2 zu = upk2(z2);
            float sz = zu.x + zu.y;

            ulonglong2 wnv = wi2[gn];
            ull i2 = fma2(X01, wnv.x, pk2(dsm[BIN_OFF + g], 0.f));
            i2 = fma2(X23, wnv.y, i2);
            float2 iu = upk2(i2);
            float gi = iu.x + iu.y;

            ull g2 = pk2(dsm[BHN_OFF + g], 0.f);
            const ulonglong2* wnp = (const ulonglong2*)&dsm[WHH_OFF + gn * 32];
#pragma unroll
            for (int q = 0; q < 8; q++) {
                ulonglong2 wv = wnp[(q + gn) & 7];
                g2 = fma2(hp[2 * q + 0], wv.x, g2);
                g2 = fma2(hp[2 * q + 1], wv.y, g2);
            }
            float2 gu = upk2(g2);
            float gh = gu.x + gu.y;

            float r = fsigmoid(sr);
            float z = fsigmoid(sz);
            float n = ftanh(fmaf(r, gh, gi));
            float2 hpair = upk2(hp[2 * k + (s >> 1)]);
            float hold = (s & 1) ? hpair.y : hpair.x;
            float hnew = fmaf(z, hold - n, n);
            rbuf[g] = hnew;
            po = fmaf(hnew, dsm[FCW_OFF + g], po);
        }
        po += __shfl_xor_sync(0xffffffffu, po, 8);
        po += __shfl_xor_sync(0xffffffffu, po, 16);
        float o = dsm[FCB_OFF] + po;

        __syncwarp();
#pragma unroll
        for (int q = 0; q < 8; q++) {
            ulonglong2 hv = rb2[q];
            hp[2 * q + 0] = hv.x;
            hp[2 * q + 1] = hv.y;
        }
        __syncwarp();

        if (s == 0) out[(size_t)t * B + b] = o;
        if (t < TDEC - 1) {
            float4 yn = *(const float4*)(y + (size_t)b * 52 + (t + 1) * 4);
            xA = yn.y; xB = yn.z; xC = yn.w; xD = o;
        }
    }

    // self-reset counters for next graph replay
    __syncthreads();
    if (tid == 0) {
        int v = atomicAdd(&g_done[chunk], 1);
        if (v == DB_PER_CHUNK - 1) {
            g_cnt[chunk] = 0;
            g_done[chunk] = 0;
        }
    }
}

__global__ __launch_bounds__(256, 2)
void fused_kernel(const float* __restrict__ y,
                  const float* __restrict__ enc,
                  const float* __restrict__ hidden,
                  const float* __restrict__ attn_W, const float* __restrict__ attn_b,
                  const float* __restrict__ comb_W, const float* __restrict__ comb_b,
                  const float* __restrict__ w_ih, const float* __restrict__ w_hh,
                  const float* __restrict__ b_ih, const float* __restrict__ b_hh,
                  const float* __restrict__ fc_W, const float* __restrict__ fc_b,
                  float* __restrict__ out)
{
    extern __shared__ __align__(16) float dsm[];
    const int bid = blockIdx.x;
    const int chunk = bid / CB;
    const int r = bid % CB;
    if (r < PB_PER_CHUNK) {
        precompute_role(chunk, r, enc, comb_W, dsm);
    } else {
        decoder_role(chunk, r - PB_PER_CHUNK, y, hidden, attn_W, attn_b, comb_W,
                     comb_b, w_ih, w_hh, b_ih, b_hh, fc_W, fc_b, out, dsm);
    }
}

extern "C" void kernel_launch(void* const* d_in, const int* in_sizes, int n_in,
                              void* d_out, int out_size) {
    const float* y      = (const float*)d_in[0];
    const float* enc    = (const float*)d_in[1];
    const float* hidden = (const float*)d_in[2];
    // d_in[3] = batch_ids (unused)
    const float* attn_W = (const float*)d_in[4];
    const float* attn_b = (const float*)d_in[5];
    const float* comb_W = (const float*)d_in[6];
    const float* comb_b = (const float*)d_in[7];
    const float* w_ih   = (const float*)d_in[8];
    const float* w_hh   = (const float*)d_in[9];
    const float* b_ih   = (const float*)d_in[10];
    const float* b_hh   = (const float*)d_in[11];
    const float* fc_W   = (const float*)d_in[12];
    const float* fc_b   = (const float*)d_in[13];

    const int smem_bytes = SMEM_FLOATS * 4;
    cudaFuncSetAttribute(fused_kernel, cudaFuncAttributeMaxDynamicSharedMemorySize,
                         smem_bytes);

    fused_kernel<<<NCHUNK * CB, 256, smem_bytes>>>(y, enc, hidden, attn_W, attn_b,
                                                   comb_W, comb_b, w_ih, w_hh,
                                                   b_ih, b_hh, fc_W, fc_b,
                                                   (float*)d_out);
}

// round 12
// speedup vs baseline: 1.2745x; 1.2745x over previous
#include <cuda_runtime.h>
#include <cuda_pipeline.h>
#include <math.h>

#define B 16384
#define TDEC 12

typedef unsigned long long ull;

// P[e][b][i] = dot(comb_W[i][0:128], enc[e][b][:]) — 12.6 MB scratch (L2-resident)
__device__ __align__(16) float g_P[48 * B * 4];

// ---- f32x2 packed math (sm_103a) ----
__device__ __forceinline__ ull fma2(ull a, ull b, ull c) {
    ull d;
    asm("fma.rn.f32x2 %0, %1, %2, %3;" : "=l"(d) : "l"(a), "l"(b), "l"(c));
    return d;
}
__device__ __forceinline__ ull add2(ull a, ull b) {
    ull d;
    asm("add.rn.f32x2 %0, %1, %2;" : "=l"(d) : "l"(a), "l"(b));
    return d;
}
__device__ __forceinline__ ull pk2(float lo, float hi) {
    ull r;
    asm("mov.b64 %0, {%1, %2};" : "=l"(r) : "f"(lo), "f"(hi));
    return r;
}
__device__ __forceinline__ float2 upk2(ull v) {
    float2 f;
    asm("mov.b64 {%0, %1}, %2;" : "=f"(f.x), "=f"(f.y) : "l"(v));
    return f;
}
__device__ __forceinline__ float tanh_ap(float x) {
    float r;
    asm("tanh.approx.f32 %0, %1;" : "=f"(r) : "f"(x));
    return r;
}

// ====== kernel 1: cp.async double-buffered P precompute (R10, measured 80us) ==
__global__ __launch_bounds__(256) void precompute_P(const float* __restrict__ enc,
                                                    const float* __restrict__ comb_W)
{
    __shared__ __align__(16) float tile[2][64 * 132];
    __shared__ __align__(16) float wT[33 * 20];

    const int tid = threadIdx.x;
    const int w = tid >> 5;
    const int lane = tid & 31;

    for (int idx = tid; idx < 512; idx += 256) {
        int q = idx >> 4, i = (idx >> 2) & 3, j = idx & 3;
        wT[q * 20 + i * 4 + j] = comb_W[i * 132 + q * 4 + j];
    }

    const size_t base = (size_t)blockIdx.x * 256;
    const float4* ebase = (const float4*)enc;

#pragma unroll
    for (int r = 0; r < 8; r++) {
        size_t row = base + w * 8 + r;
        __pipeline_memcpy_async(&tile[0][(w * 8 + r) * 132 + lane * 4],
                                &ebase[row * 32 + lane], 16);
    }
    __pipeline_commit();

    for (int ti = 0; ti < 4; ti++) {
        const int buf = ti & 1;
        __pipeline_wait_prior(0);
        __syncthreads();
        if (ti < 3) {
#pragma unroll
            for (int r = 0; r < 8; r++) {
                size_t row = base + (size_t)(ti + 1) * 64 + w * 8 + r;
                __pipeline_memcpy_async(&tile[buf ^ 1][(w * 8 + r) * 132 + lane * 4],
                                        &ebase[row * 32 + lane], 16);
            }
            __pipeline_commit();
        }

        const int rl = w * 8 + (lane >> 2);
        const int c = lane & 3;
        float s0 = 0.f, s1 = 0.f, s2 = 0.f, s3 = 0.f;
#pragma unroll
        for (int k = 0; k < 8; k++) {
            int kp = (k + 2 * c) & 7;
            int q = 8 * c + kp;
            float4 v  = *(const float4*)&tile[buf][rl * 132 + q * 4];
            float4 w0 = *(const float4*)&wT[q * 20 + 0];
            float4 w1 = *(const float4*)&wT[q * 20 + 4];
            float4 w2 = *(const float4*)&wT[q * 20 + 8];
            float4 w3 = *(const float4*)&wT[q * 20 + 12];
            s0 = fmaf(v.x, w0.x, s0); s0 = fmaf(v.y, w0.y, s0); s0 = fmaf(v.z, w0.z, s0); s0 = fmaf(v.w, w0.w, s0);
            s1 = fmaf(v.x, w1.x, s1); s1 = fmaf(v.y, w1.y, s1); s1 = fmaf(v.z, w1.z, s1); s1 = fmaf(v.w, w1.w, s1);
            s2 = fmaf(v.x, w2.x, s2); s2 = fmaf(v.y, w2.y, s2); s2 = fmaf(v.z, w2.z, s2); s2 = fmaf(v.w, w2.w, s2);
            s3 = fmaf(v.x, w3.x, s3); s3 = fmaf(v.y, w3.y, s3); s3 = fmaf(v.z, w3.z, s3); s3 = fmaf(v.w, w3.w, s3);
        }
        s0 += __shfl_xor_sync(0xffffffffu, s0, 1); s0 += __shfl_xor_sync(0xffffffffu, s0, 2);
        s1 += __shfl_xor_sync(0xffffffffu, s1, 1); s1 += __shfl_xor_sync(0xffffffffu, s1, 2);
        s2 += __shfl_xor_sync(0xffffffffu, s2, 1); s2 += __shfl_xor_sync(0xffffffffu, s2, 2);
        s3 += __shfl_xor_sync(0xffffffffu, s3, 1); s3 += __shfl_xor_sync(0xffffffffu, s3, 2);

        float v = s0;
        if (c == 1) v = s1; else if (c == 2) v = s2; else if (c == 3) v = s3;
        g_P[(base + (size_t)ti * 64) * 4 + w * 32 + lane] = v;
        __syncthreads();
    }
}

// ================= kernel 2: R7 decoder + fast activations ===================
__device__ __forceinline__ float nfix(float v) {
    if (isnan(v)) return 0.f;
    return fminf(fmaxf(v, -3.4028234663852886e38f), 3.4028234663852886e38f);
}

#define AW_OFF   0
#define AB_OFF   1728
#define WHH_OFF  1776
#define WIH_OFF  4848
#define BRZ_OFF  5232
#define BIN_OFF  5296
#define BHN_OFF  5328
#define CWX_OFF  5360
#define CB_OFF   5376
#define FCW_OFF  5380
#define FCB_OFF  5412
#define P_OFF    5424
#define RB_OFF   18480
#define SMEM_FLOATS (18480 + 8 * 288)

__global__ __launch_bounds__(256, 2)
void decoder_loop(const float* __restrict__ y,
                  const float* __restrict__ hidden,
                  const float* __restrict__ attn_W, const float* __restrict__ attn_b,
                  const float* __restrict__ comb_W, const float* __restrict__ comb_b,
                  const float* __restrict__ w_ih, const float* __restrict__ w_hh,
                  const float* __restrict__ b_ih, const float* __restrict__ b_hh,
                  const float* __restrict__ fc_W, const float* __restrict__ fc_b,
                  float* __restrict__ out)
{
    extern __shared__ __align__(16) float dsm[];
    const int tid = threadIdx.x;
    const int w = tid >> 5;
    const int lane = tid & 31;
    const int s = lane >> 3;
    const int el = lane & 7;
    const int b0blk = blockIdx.x * 64;
    const int b = b0blk + w * 8 + el;

    for (int i = tid; i < 1728; i += 256) dsm[AW_OFF + i] = attn_W[i];
    if (tid < 48) dsm[AB_OFF + tid] = attn_b[tid];
    for (int i = tid; i < 3072; i += 256) {
        int g = i >> 5, j = i & 31, q = j >> 2, r = j & 3;
        dsm[WHH_OFF + g * 32 + (((q + g) & 7) << 2) + r] = w_hh[i];
    }
    for (int i = tid; i < 384; i += 256) dsm[WIH_OFF + i] = w_ih[i];
    if (tid < 64) dsm[BRZ_OFF + tid] = b_ih[tid] + b_hh[tid];
    else if (tid < 96) {
        dsm[BIN_OFF + tid - 64] = b_ih[tid];
        dsm[BHN_OFF + tid - 64] = b_hh[tid];
    }
    if (tid < 16) dsm[CWX_OFF + tid] = comb_W[(tid >> 2) * 132 + 128 + (tid & 3)];
    if (tid < 4) dsm[CB_OFF + tid] = comb_b[tid];
    if (tid < 32) dsm[FCW_OFF + tid] = fc_W[tid];
    if (tid == 0) dsm[FCB_OFF] = fc_b[0];
    {
        float4* Pd = (float4*)&dsm[P_OFF];
        const float4* gP4 = (const float4*)g_P;
        for (int i = tid; i < 48 * 64; i += 256) {
            int e = i >> 6, pc = i & 63;
            Pd[pc * 51 + e] = __ldg(&gP4[(size_t)e * B + b0blk + pc]);
        }
    }
    __syncthreads();   // only block barrier

    ull hp[16];
#pragma unroll
    for (int q = 0; q < 8; q++) {
        float4 hv = *(const float4*)(hidden + (size_t)b * 32 + 4 * q);
        hp[2 * q + 0] = pk2(hv.x, hv.y);
        hp[2 * q + 1] = pk2(hv.z, hv.w);
    }

    float4 yv = *(const float4*)(y + (size_t)b * 52);
    float xA = nfix(yv.x), xB = nfix(yv.y), xC = nfix(yv.z), xD = nfix(yv.w);

    const ulonglong2* Pw2 = (const ulonglong2*)&dsm[P_OFF];
    const int prow = (w * 8 + el) * 51;
    float* rbuf = &dsm[RB_OFF + w * 288 + el * 36];
    const ulonglong2* rb2 = (const ulonglong2*)rbuf;

    for (int t = 0; t < TDEC; t++) {
        ull xab = pk2(xA, xB), xcd = pk2(xC, xD);

        float ss = 0.f;
        ull c01 = 0, c23 = 0;
#pragma unroll
        for (int j = 0; j < 12; j++) {
            const int e = 4 * j + s;
            const ulonglong2* awr2 = (const ulonglong2*)&dsm[AW_OFF + e * 36];
            ull acc2 = pk2(dsm[AB_OFF + e], 0.f);
            ulonglong2 w0 = awr2[0];
            acc2 = fma2(xab, w0.x, acc2);
            acc2 = fma2(xcd, w0.y, acc2);
#pragma unroll
            for (int q = 0; q < 8; q++) {
                ulonglong2 wv = awr2[1 + q];
                acc2 = fma2(hp[2 * q + 0], wv.x, acc2);
                acc2 = fma2(hp[2 * q + 1], wv.y, acc2);
            }
            float2 ac = upk2(acc2);
            float ev = __expf(ac.x + ac.y);
            ss += ev;
            ull evv = pk2(ev, ev);
            ulonglong2 pv = Pw2[prow + e];
            c01 = fma2(evv, pv.x, c01);
            c23 = fma2(evv, pv.y, c23);
        }
#pragma unroll
        for (int o = 8; o <= 16; o <<= 1) {
            ss += __shfl_xor_sync(0xffffffffu, ss, o);
            c01 = add2(c01, __shfl_xor_sync(0xffffffffu, c01, o));
            c23 = add2(c23, __shfl_xor_sync(0xffffffffu, c23, o));
        }

        float inv = __fdividef(1.f, ss);
        float2 cA = upk2(c01), cB = upk2(c23);
        float4 cw0 = *(const float4*)&dsm[CWX_OFF + 0];
        float4 cw1 = *(const float4*)&dsm[CWX_OFF + 4];
        float4 cw2 = *(const float4*)&dsm[CWX_OFF + 8];
        float4 cw3 = *(const float4*)&dsm[CWX_OFF + 12];
        float X0 = fmaf(cA.x, inv, dsm[CB_OFF + 0]);
        X0 = fmaf(xA, cw0.x, X0); X0 = fmaf(xB, cw0.y, X0); X0 = fmaf(xC, cw0.z, X0); X0 = fmaf(xD, cw0.w, X0);
        float X1 = fmaf(cA.y, inv, dsm[CB_OFF + 1]);
        X1 = fmaf(xA, cw1.x, X1); X1 = fmaf(xB, cw1.y, X1); X1 = fmaf(xC, cw1.z, X1); X1 = fmaf(xD, cw1.w, X1);
        float X2 = fmaf(cB.x, inv, dsm[CB_OFF + 2]);
        X2 = fmaf(xA, cw2.x, X2); X2 = fmaf(xB, cw2.y, X2); X2 = fmaf(xC, cw2.z, X2); X2 = fmaf(xD, cw2.w, X2);
        float X3 = fmaf(cB.y, inv, dsm[CB_OFF + 3]);
        X3 = fmaf(xA, cw3.x, X3); X3 = fmaf(xB, cw3.y, X3); X3 = fmaf(xC, cw3.z, X3); X3 = fmaf(xD, cw3.w, X3);
        ull X01 = pk2(X0, X1), X23 = pk2(X2, X3);

        float po = 0.f;
        const ulonglong2* wi2 = (const ulonglong2*)&dsm[WIH_OFF];
#pragma unroll
        for (int k = 0; k < 8; k++) {
            const int g = 4 * k + s;
            const int gz = 32 + g, gn = 64 + g;

            ulonglong2 wiv = wi2[g];
            ull a2 = fma2(X01, wiv.x, pk2(dsm[BRZ_OFF + g], 0.f));
            a2 = fma2(X23, wiv.y, a2);
            const ulonglong2* wp = (const ulonglong2*)&dsm[WHH_OFF + g * 32];
#pragma unroll
            for (int q = 0; q < 8; q++) {
                ulonglong2 wv = wp[(q + g) & 7];
                a2 = fma2(hp[2 * q + 0], wv.x, a2);
                a2 = fma2(hp[2 * q + 1], wv.y, a2);
            }
            float2 au = upk2(a2);
            float sr = au.x + au.y;

            ulonglong2 wzv = wi2[gz];
            ull z2 = fma2(X01, wzv.x, pk2(dsm[BRZ_OFF + gz], 0.f));
            z2 = fma2(X23, wzv.y, z2);
            const ulonglong2* wzp = (const ulonglong2*)&dsm[WHH_OFF + gz * 32];
#pragma unroll
            for (int q = 0; q < 8; q++) {
                ulonglong2 wv = wzp[(q + gz) & 7];
                z2 = fma2(hp[2 * q + 0], wv.x, z2);
                z2 = fma2(hp[2 * q + 1], wv.y, z2);
            }
            float2 zu = upk2(z2);
            float sz = zu.x + zu.y;

            ulonglong2 wnv = wi2[gn];
            ull i2 = fma2(X01, wnv.x, pk2(dsm[BIN_OFF + g], 0.f));
            i2 = fma2(X23, wnv.y, i2);
            float2 iu = upk2(i2);
            float gi = iu.x + iu.y;

            ull g2 = pk2(dsm[BHN_OFF + g], 0.f);
            const ulonglong2* wnp = (const ulonglong2*)&dsm[WHH_OFF + gn * 32];
#pragma unroll
            for (int q = 0; q < 8; q++) {
                ulonglong2 wv = wnp[(q + gn) & 7];
                g2 = fma2(hp[2 * q + 0], wv.x, g2);
                g2 = fma2(hp[2 * q + 1], wv.y, g2);
            }
            float2 gu = upk2(g2);
            float gh = gu.x + gu.y;

            // sigmoid(s) = 0.5 + 0.5*tanh(0.5*s); tanh via MUFU
            float r = fmaf(tanh_ap(0.5f * sr), 0.5f, 0.5f);
            float z = fmaf(tanh_ap(0.5f * sz), 0.5f, 0.5f);
            float n = tanh_ap(fmaf(r, gh, gi));
            float2 hpair = upk2(hp[2 * k + (s >> 1)]);
            float hold = (s & 1) ? hpair.y : hpair.x;
            float hnew = fmaf(z, hold - n, n);
            rbuf[g] = hnew;
            po = fmaf(hnew, dsm[FCW_OFF + g], po);
        }
        po += __shfl_xor_sync(0xffffffffu, po, 8);
        po += __shfl_xor_sync(0xffffffffu, po, 16);
        float o = dsm[FCB_OFF] + po;

        __syncwarp();
#pragma unroll
        for (int q = 0; q < 8; q++) {
            ulonglong2 hv = rb2[q];
            hp[2 * q + 0] = hv.x;
            hp[2 * q + 1] = hv.y;
        }
        __syncwarp();

        if (s == 0) out[(size_t)t * B + b] = o;
        if (t < TDEC - 1) {
            float4 yn = *(const float4*)(y + (size_t)b * 52 + (t + 1) * 4);
            xA = yn.y; xB = yn.z; xC = yn.w; xD = o;
        }
    }
}

extern "C" void kernel_launch(void* const* d_in, const int* in_sizes, int n_in,
                              void* d_out, int out_size) {
    const float* y      = (const float*)d_in[0];
    const float* enc    = (const float*)d_in[1];
    const float* hidden = (const float*)d_in[2];
    // d_in[3] = batch_ids (unused)
    const float* attn_W = (const float*)d_in[4];
    const float* attn_b = (const float*)d_in[5];
    const float* comb_W = (const float*)d_in[6];
    const float* comb_b = (const float*)d_in[7];
    const float* w_ih   = (const float*)d_in[8];
    const float* w_hh   = (const float*)d_in[9];
    const float* b_ih   = (const float*)d_in[10];
    const float* b_hh   = (const float*)d_in[11];
    const float* fc_W   = (const float*)d_in[12];
    const float* fc_b   = (const float*)d_in[13];

    const int smem_bytes = SMEM_FLOATS * 4;
    cudaFuncSetAttribute(decoder_loop, cudaFuncAttributeMaxDynamicSharedMemorySize,
                         smem_bytes);

    precompute_P<<<(48 * B) / 256, 256>>>(enc, comb_W);
    decoder_loop<<<B / 64, 256, smem_bytes>>>(y, hidden, attn_W, attn_b, comb_W,
                                              comb_b, w_ih, w_hh, b_ih, b_hh,
                                              fc_W, fc_b, (float*)d_out);
}